// round 15
// baseline (speedup 1.0000x reference)
#include <cuda_runtime.h>
#include <cstdint>

// ---------------------------------------------------------------------------
// MQNet round 15: FFMA2 GEMM v4 — 512-thread CTAs for 2x occupancy.
//   R13: 34 TF/s = 51% of packed ceiling, issue 40% @ ~3 warps/SMSP.
//   R14: A-duplication cost + no extra CTAs => regression.
//   This round: 128x128 tile, 512 threads, 4x8 outputs/thread (32 acc regs),
//   <=64 regs (launch_bounds 512,2) -> 2 CTAs/SM = 8 warps/SMSP.
//   Inner kk: 4 LDS.64(A dup) + 8 LDS.32(B bcast) + 4 packs + 16 FFMA2
//   = 32 issue slots vs 32 fma-pipe cycles: issue-balanced at 8 warps/SMSP.
//   Per-element strict k-order retained => rel_err exactly 3.496532e-05.
// ---------------------------------------------------------------------------

#define NN 8192
#define HH 512
#define H3 1536
#define BS 20
#define BK 16

// ------------------------- device scratch (no mallocs) ---------------------
__device__ float g_xw[NN * HH];
__device__ float g_feats[NN * HH];
__device__ float g_gcn[NN * HH];
__device__ float g_gi[(size_t)NN * H3];
__device__ float g_h[HH];
__device__ float g_gh[H3];
__device__ unsigned long long g_key;
__device__ int g_mask[NN];

// ------------------------- helpers -----------------------------------------
__device__ __forceinline__ unsigned ford(float f) {
    unsigned u = __float_as_uint(f);
    return (u & 0x80000000u) ? ~u : (u | 0x80000000u);
}
__device__ __forceinline__ float forddec(unsigned u) {
    return (u & 0x80000000u) ? __uint_as_float(u & 0x7FFFFFFFu)
                             : __uint_as_float(~u);
}
__device__ __forceinline__ float sigf(float x) {
    return 1.0f / (1.0f + __expf(-x));
}
__device__ __forceinline__ float tanh_f(float x) {
    return 1.0f - 2.0f / (1.0f + __expf(2.0f * x));
}
__device__ __forceinline__ unsigned long long pack2(float lo, float hi) {
    unsigned long long r;
    asm("mov.b64 %0, {%1, %2};" : "=l"(r) : "f"(lo), "f"(hi));
    return r;
}
__device__ __forceinline__ void unpack2(unsigned long long v, float& lo,
                                        float& hi) {
    asm("mov.b64 {%0, %1}, %2;" : "=f"(lo), "=f"(hi) : "l"(v));
}
// packed dual fp32 FMA: d = a*b + d, each 32-bit lane an exact fma.rn.f32
__device__ __forceinline__ void ffma2(unsigned long long& d,
                                      unsigned long long a,
                                      unsigned long long b) {
    asm volatile("fma.rn.f32x2 %0, %1, %2, %3;"
                 : "=l"(d) : "l"(a), "l"(b), "l"(d));
}

// ------------------------- FFMA2 SGEMM v4 (bitwise == R1) -------------------
// C[M,N] = A[M,K] * op(B) (+bias) (relu).
//   BT=false: B is [K,N]; BT=true: B is [N,K] (use B^T).
// 512 threads: tx = t&15 (n base), ty = t>>4 (m group of 4 rows).
// Per thread: rows m0+ty*4+{0..3}, cols n0 + c*16 + tx for c=0..7
// (pairs (2j,2j+1) packed into f32x2).
// A SMEM: duplicated pairs As2[kk][m] = (v,v), stride 129 float2.
// B SMEM: R1 scalar layout Bs[kk][n].
template <bool BT, int EPI>  // EPI: 0 none, 1 +bias, 2 +bias & relu
__global__ void __launch_bounds__(512, 2)
sgemm_v4(const float* __restrict__ A, const float* __restrict__ B,
         const float* __restrict__ bias, float* __restrict__ C,
         int M, int N, int K) {
    __shared__ float2 As2[BK][129];   // 16.5 KB
    __shared__ float Bs[BK][128];     // 8 KB

    const int t = threadIdx.x;
    const int tx = t & 15;
    const int ty = t >> 4;            // 0..31
    const int m0 = blockIdx.y * 128;
    const int n0 = blockIdx.x * 128;

    unsigned long long acc2[4][4];
#pragma unroll
    for (int i = 0; i < 4; i++)
#pragma unroll
        for (int j = 0; j < 4; j++) acc2[i][j] = 0ull;  // (+0.f, +0.f)

    const float* Ab = A + (size_t)m0 * K;

    for (int k0 = 0; k0 < K; k0 += BK) {
        // ---- load A tile (128x16): one float4 per thread, store (v,v) ----
        {
            int row = t >> 2;                // 0..127
            int kc = (t & 3) * 4;            // 0,4,8,12
            float4 v = *reinterpret_cast<const float4*>(
                Ab + (size_t)row * K + k0 + kc);
            As2[kc + 0][row] = make_float2(v.x, v.x);
            As2[kc + 1][row] = make_float2(v.y, v.y);
            As2[kc + 2][row] = make_float2(v.z, v.z);
            As2[kc + 3][row] = make_float2(v.w, v.w);
        }
        // ---- load B tile (16x128): one float4 per thread ----
        if (!BT) {
            int row = t >> 5;                // k: 0..15
            int c = (t & 31) * 4;            // n: 0..124
            float4 v = *reinterpret_cast<const float4*>(
                B + (size_t)(k0 + row) * N + n0 + c);
            *reinterpret_cast<float4*>(&Bs[row][c]) = v;
        } else {
            int rn = t >> 2;                 // n: 0..127
            int kc = (t & 3) * 4;
            float4 v = *reinterpret_cast<const float4*>(
                B + (size_t)(n0 + rn) * K + k0 + kc);
            Bs[kc + 0][rn] = v.x;
            Bs[kc + 1][rn] = v.y;
            Bs[kc + 2][rn] = v.z;
            Bs[kc + 3][rn] = v.w;
        }
        __syncthreads();

        // ---- inner: 4 LDS.64(A) + 8 LDS.32(B) + 4 packs + 16 FFMA2 ----
#pragma unroll
        for (int kk = 0; kk < BK; kk++) {
            unsigned long long a2[4], b2[4];
#pragma unroll
            for (int i = 0; i < 4; i++)
                a2[i] = *reinterpret_cast<const unsigned long long*>(
                    &As2[kk][ty * 4 + i]);
            float rb[8];
#pragma unroll
            for (int c = 0; c < 8; c++) rb[c] = Bs[kk][c * 16 + tx];
#pragma unroll
            for (int j = 0; j < 4; j++)
                b2[j] = pack2(rb[2 * j], rb[2 * j + 1]);
#pragma unroll
            for (int i = 0; i < 4; i++)
#pragma unroll
                for (int j = 0; j < 4; j++) ffma2(acc2[i][j], a2[i], b2[j]);
        }
        __syncthreads();
    }

    // ---------------- epilogue (same per-element arithmetic as R1) ----------
#pragma unroll
    for (int i = 0; i < 4; i++) {
        int m = m0 + ty * 4 + i;
#pragma unroll
        for (int j = 0; j < 4; j++) {
            float v0, v1;
            unpack2(acc2[i][j], v0, v1);
            int nlo = n0 + (2 * j) * 16 + tx;
            int nhi = n0 + (2 * j + 1) * 16 + tx;
            if (EPI >= 1) { v0 += bias[nlo]; v1 += bias[nhi]; }
            if (EPI == 2) { v0 = fmaxf(v0, 0.f); v1 = fmaxf(v1, 0.f); }
            C[(size_t)m * N + nlo] = v0;
            C[(size_t)m * N + nhi] = v1;
        }
    }
}

// ------------------------- init: mask=1, key=0 ------------------------------
__global__ void init_kernel() {
    int i = blockIdx.x * blockDim.x + threadIdx.x;
    if (i < NN) g_mask[i] = 1;
    if (i == 0) g_key = 0ull;
}

// ------------------------- step-0 GEMV + argmax (verbatim R1) ---------------
__global__ void __launch_bounds__(256)
gemv_argmax_kernel(const float* __restrict__ w, const float* __restrict__ b) {
    __shared__ float sw[HH];
    __shared__ unsigned long long skey[8];
    int t = threadIdx.x;
    for (int j = t; j < HH; j += 256) sw[j] = w[j];
    __syncthreads();

    int wid = t >> 5, lane = t & 31;
    int i = blockIdx.x * 8 + wid;
    const float* row = g_gcn + (size_t)i * HH;
    float acc = 0.f;
#pragma unroll 4
    for (int jj = 0; jj < 16; jj++) {
        int j = lane + jj * 32;
        acc += row[j] * sw[j];
    }
#pragma unroll
    for (int o = 16; o; o >>= 1) acc += __shfl_down_sync(0xffffffffu, acc, o);
    if (lane == 0) {
        float v = acc + b[0];
        skey[wid] = ((unsigned long long)ford(v) << 32) |
                    (0xFFFFFFFFu - (unsigned)i);
    }
    __syncthreads();
    if (t == 0) {
        unsigned long long best = skey[0];
#pragma unroll
        for (int w2 = 1; w2 < 8; w2++) best = best > skey[w2] ? best : skey[w2];
        atomicMax(&g_key, best);
    }
}

// ------------------------- gh = h @ W_hh^T + b_hh (verbatim R1) -------------
__global__ void __launch_bounds__(256)
gh_kernel(const float* __restrict__ Whh, const float* __restrict__ bhh) {
    __shared__ float sh[HH];
    int t = threadIdx.x;
    for (int j = t; j < HH; j += 256) sh[j] = g_h[j];
    __syncthreads();
    int wid = t >> 5, lane = t & 31;
    int o = blockIdx.x * 8 + wid;
    const float* wr = Whh + (size_t)o * HH;
    float acc = 0.f;
#pragma unroll 4
    for (int jj = 0; jj < 16; jj++) {
        int j = lane + jj * 32;
        acc += wr[j] * sh[j];
    }
#pragma unroll
    for (int off = 16; off; off >>= 1)
        acc += __shfl_down_sync(0xffffffffu, acc, off);
    if (lane == 0) g_gh[o] = acc + bhh[o];
}

// ------------------------- GRU elementwise + vals + argmax (verbatim R1) ----
__global__ void __launch_bounds__(256)
gru_vals_kernel(const float* __restrict__ w2, const float* __restrict__ b2) {
    __shared__ float sgh[H3];
    __shared__ float sh[HH];
    __shared__ float sw[HH];
    __shared__ unsigned long long skey[8];
    int t = threadIdx.x;
    for (int j = t; j < H3; j += 256) sgh[j] = g_gh[j];
    for (int j = t; j < HH; j += 256) {
        sh[j] = g_h[j];
        sw[j] = w2[j];
    }
    __syncthreads();

    int wid = t >> 5, lane = t & 31;
    int i = blockIdx.x * 8 + wid;
    unsigned long long key = 0ull;
    if (g_mask[i]) {
        const float* gi = g_gi + (size_t)i * H3;
        float acc = 0.f;
#pragma unroll 4
        for (int jj = 0; jj < 16; jj++) {
            int j = lane + jj * 32;
            float r = sigf(gi[j] + sgh[j]);
            float z = sigf(gi[j + 512] + sgh[j + 512]);
            float ng = tanh_f(gi[j + 1024] + r * sgh[j + 1024]);
            float rnn = (1.f - z) * ng + z * sh[j];
            acc += sw[j] * rnn;
        }
#pragma unroll
        for (int o = 16; o; o >>= 1) acc += __shfl_down_sync(0xffffffffu, acc, o);
        if (lane == 0) {
            float v = acc + b2[0];
            key = ((unsigned long long)ford(v) << 32) |
                  (0xFFFFFFFFu - (unsigned)i);
        }
    }
    if (lane == 0) skey[wid] = key;
    __syncthreads();
    if (t == 0) {
        unsigned long long best = skey[0];
#pragma unroll
        for (int w = 1; w < 8; w++) best = best > skey[w] ? best : skey[w];
        atomicMax(&g_key, best);
    }
}

// ------------------------- select (verbatim R1) -----------------------------
__global__ void __launch_bounds__(512)
select_kernel(float* __restrict__ out, int step, int first) {
    __shared__ int sidx;
    int t = threadIdx.x;
    if (t == 0) {
        unsigned long long key = g_key;
        int idx = (int)(0xFFFFFFFFu - (unsigned)(key & 0xFFFFFFFFull));
        float v = forddec((unsigned)(key >> 32));
        out[step] = (float)idx;
        out[BS + step] = v;
        g_mask[idx] = 0;
        g_key = 0ull;
        sidx = idx;
    }
    __syncthreads();
    int idx = sidx;
    int j = t;
    if (first) {
        g_h[j] = g_gcn[(size_t)idx * HH + j];
    } else {
        const float* gi = g_gi + (size_t)idx * H3;
        float r = sigf(gi[j] + g_gh[j]);
        float z = sigf(gi[j + 512] + g_gh[j + 512]);
        float ng = tanh_f(gi[j + 1024] + r * g_gh[j + 1024]);
        g_h[j] = (1.f - z) * ng + z * g_h[j];
    }
}

// ------------------------- launch ------------------------------------------
extern "C" void kernel_launch(void* const* d_in, const int* in_sizes, int n_in,
                              void* d_out, int out_size) {
    (void)in_sizes; (void)n_in; (void)out_size;
    const float* state  = (const float*)d_in[0];
    const float* adj    = (const float*)d_in[1];
    const float* W1     = (const float*)d_in[3];
    const float* b1     = (const float*)d_in[4];
    const float* W2     = (const float*)d_in[5];
    const float* b2     = (const float*)d_in[6];
    const float* w_out1 = (const float*)d_in[7];
    const float* b_out1 = (const float*)d_in[8];
    const float* w_out2 = (const float*)d_in[9];
    const float* b_out2 = (const float*)d_in[10];
    const float* W_ih   = (const float*)d_in[11];
    const float* W_hh   = (const float*)d_in[12];
    const float* b_ih   = (const float*)d_in[13];
    const float* b_hh   = (const float*)d_in[14];
    float* out = (float*)d_out;

    float *xw, *feats, *gcn, *gi;
    cudaGetSymbolAddress((void**)&xw, g_xw);
    cudaGetSymbolAddress((void**)&feats, g_feats);
    cudaGetSymbolAddress((void**)&gcn, g_gcn);
    cudaGetSymbolAddress((void**)&gi, g_gi);

    dim3 blk(512);

    init_kernel<<<(NN + 255) / 256, 256>>>();

    // G1: XW = state @ W1
    sgemm_v4<false, 0><<<dim3(HH / 128, NN / 128), blk>>>(
        state, W1, nullptr, xw, NN, HH, HH);
    // G2: feats = relu(adj @ XW + b1)
    sgemm_v4<false, 2><<<dim3(HH / 128, NN / 128), blk>>>(
        adj, xw, b1, feats, NN, HH, NN);
    // G3: XW = feats @ W2
    sgemm_v4<false, 0><<<dim3(HH / 128, NN / 128), blk>>>(
        feats, W2, nullptr, xw, NN, HH, HH);
    // G4: gcn = relu(adj @ XW + b2)
    sgemm_v4<false, 2><<<dim3(HH / 128, NN / 128), blk>>>(
        adj, xw, b2, gcn, NN, HH, NN);
    // G5: gi = gcn @ W_ih^T + b_ih
    sgemm_v4<true, 1><<<dim3(H3 / 128, NN / 128), blk>>>(
        gcn, W_ih, b_ih, gi, NN, H3, HH);

    // step 0
    gemv_argmax_kernel<<<NN / 8, 256>>>(w_out1, b_out1);
    select_kernel<<<1, 512>>>(out, 0, 1);

    // steps 1..19
    for (int t = 1; t < BS; t++) {
        gh_kernel<<<H3 / 8, 256>>>(W_hh, b_hh);
        gru_vals_kernel<<<NN / 8, 256>>>(w_out2, b_out2);
        select_kernel<<<1, 512>>>(out, t, 0);
    }
}

// round 16
// speedup vs baseline: 1.1895x; 1.1895x over previous
#include <cuda_runtime.h>
#include <cstdint>

// ---------------------------------------------------------------------------
// MQNet round 16: R13 inner loop (best: G1 126us), 4x CTA count.
//   Diagnosis: grid 256 on 148 SMs = 1.73 CTAs/SM -> CTA-starved; issue holes
//   from LDS latency can't be filled (issue ~40% in all 256-CTA variants).
//   Change: 128-thread CTAs, 128(m) x 64(n) tiles -> grid 512+, 4 CTAs/SM
//   possible (launch_bounds(128,4)). Inner loop balance identical to R13:
//   16 conflict-free LDS.32 + 12 packs + 32 FFMA2 per kk.
//   Grid is n-fastest so n-CTAs sharing an A row-block co-reside -> L2 hits.
//   Per-element strict k-order retained => rel_err exactly 3.496532e-05.
// ---------------------------------------------------------------------------

#define NN 8192
#define HH 512
#define H3 1536
#define BS 20
#define BK 16
#define TM 128
#define TN 64

// ------------------------- device scratch (no mallocs) ---------------------
__device__ float g_xw[NN * HH];
__device__ float g_feats[NN * HH];
__device__ float g_gcn[NN * HH];
__device__ float g_gi[(size_t)NN * H3];
__device__ float g_h[HH];
__device__ float g_gh[H3];
__device__ unsigned long long g_key;
__device__ int g_mask[NN];

// ------------------------- helpers -----------------------------------------
__device__ __forceinline__ unsigned ford(float f) {
    unsigned u = __float_as_uint(f);
    return (u & 0x80000000u) ? ~u : (u | 0x80000000u);
}
__device__ __forceinline__ float forddec(unsigned u) {
    return (u & 0x80000000u) ? __uint_as_float(u & 0x7FFFFFFFu)
                             : __uint_as_float(~u);
}
__device__ __forceinline__ float sigf(float x) {
    return 1.0f / (1.0f + __expf(-x));
}
__device__ __forceinline__ float tanh_f(float x) {
    return 1.0f - 2.0f / (1.0f + __expf(2.0f * x));
}
__device__ __forceinline__ unsigned long long pack2(float lo, float hi) {
    unsigned long long r;
    asm("mov.b64 %0, {%1, %2};" : "=l"(r) : "f"(lo), "f"(hi));
    return r;
}
__device__ __forceinline__ void unpack2(unsigned long long v, float& lo,
                                        float& hi) {
    asm("mov.b64 {%0, %1}, %2;" : "=f"(lo), "=f"(hi) : "l"(v));
}
// packed dual fp32 FMA: d = a*b + d, each 32-bit lane an exact fma.rn.f32
__device__ __forceinline__ void ffma2(unsigned long long& d,
                                      unsigned long long a,
                                      unsigned long long b) {
    asm volatile("fma.rn.f32x2 %0, %1, %2, %3;"
                 : "=l"(d) : "l"(a), "l"(b), "l"(d));
}

// ------------------------- FFMA2 SGEMM v5 (bitwise == R1) -------------------
// C[M,N] = A[M,K] * op(B) (+bias) (relu).
//   BT=false: B is [K,N]; BT=true: B is [N,K] (use B^T).
// 128 threads, tile TM=128 x TN=64. tx = t&7, ty = t>>3 (0..15).
// Per thread: rows m0+ty*8+{0..7}, cols n0 + j*8 + tx (j=0..7), pairs packed.
// SMEM: R1 scalar layouts. All inner LDS conflict-free (broadcast).
template <bool BT, int EPI>  // EPI: 0 none, 1 +bias, 2 +bias & relu
__global__ void __launch_bounds__(128, 4)
sgemm_v5(const float* __restrict__ A, const float* __restrict__ B,
         const float* __restrict__ bias, float* __restrict__ C,
         int M, int N, int K) {
    __shared__ float As[BK][TM];   // 8 KB
    __shared__ float Bs[BK][TN];   // 4 KB

    const int t = threadIdx.x;
    const int tx = t & 7;
    const int ty = t >> 3;           // 0..15
    const int m0 = blockIdx.x * TM;  // grid.x = m tiles (slow dim is y=n? no:)
    const int n0 = blockIdx.y * TN;  // grid.y varies slower; we want n fastest
    // NOTE: launch uses grid(dim3(M/TM, N/TN)) with x=m?? -> see launch: we
    // pass dim3(N/TN, M/TM) and map x->n, y->m for n-fastest co-residency.
    // (Indexing fixed below.)

    const int mBase = blockIdx.y * TM;
    const int nBase = blockIdx.x * TN;

    unsigned long long acc2[8][4];
#pragma unroll
    for (int i = 0; i < 8; i++)
#pragma unroll
        for (int j = 0; j < 4; j++) acc2[i][j] = 0ull;  // (+0.f, +0.f)

    const float* Ab = A + (size_t)mBase * K;

    for (int k0 = 0; k0 < K; k0 += BK) {
        // ---- load A tile (128x16): 4 float4 per thread (R1 pattern) ----
#pragma unroll
        for (int i = 0; i < 4; i++) {
            int lin = t + i * 128;           // 0..511
            int row = lin >> 2;              // 0..127
            int kc = (lin & 3) * 4;          // 0,4,8,12
            float4 v = *reinterpret_cast<const float4*>(
                Ab + (size_t)row * K + k0 + kc);
            As[kc + 0][row] = v.x;
            As[kc + 1][row] = v.y;
            As[kc + 2][row] = v.z;
            As[kc + 3][row] = v.w;
        }
        // ---- load B tile (16x64): 2 float4 per thread ----
#pragma unroll
        for (int i = 0; i < 2; i++) {
            int lin = t + i * 128;           // 0..255
            if (!BT) {
                int row = lin >> 4;          // k: 0..15
                int c = (lin & 15) * 4;      // n: 0..60
                float4 v = *reinterpret_cast<const float4*>(
                    B + (size_t)(k0 + row) * N + nBase + c);
                *reinterpret_cast<float4*>(&Bs[row][c]) = v;
            } else {
                int r = lin >> 2;            // n: 0..63
                int kc = (lin & 3) * 4;
                float4 v = *reinterpret_cast<const float4*>(
                    B + (size_t)(nBase + r) * K + k0 + kc);
                Bs[kc + 0][r] = v.x;
                Bs[kc + 1][r] = v.y;
                Bs[kc + 2][r] = v.z;
                Bs[kc + 3][r] = v.w;
            }
        }
        __syncthreads();

        // ---- inner: 16 conflict-free LDS.32 + 12 packs + 32 FFMA2 ----
#pragma unroll
        for (int kk = 0; kk < BK; kk++) {
            float ra[8], rb[8];
#pragma unroll
            for (int i = 0; i < 8; i++) ra[i] = As[kk][ty * 8 + i];
#pragma unroll
            for (int j = 0; j < 8; j++) rb[j] = Bs[kk][j * 8 + tx];
            unsigned long long a2[8], b2[4];
#pragma unroll
            for (int i = 0; i < 8; i++) a2[i] = pack2(ra[i], ra[i]);
#pragma unroll
            for (int j = 0; j < 4; j++)
                b2[j] = pack2(rb[2 * j], rb[2 * j + 1]);
#pragma unroll
            for (int i = 0; i < 8; i++)
#pragma unroll
                for (int j = 0; j < 4; j++) ffma2(acc2[i][j], a2[i], b2[j]);
        }
        __syncthreads();
    }

    // ---------------- epilogue (same per-element arithmetic as R1) ----------
#pragma unroll
    for (int i = 0; i < 8; i++) {
        int m = mBase + ty * 8 + i;
#pragma unroll
        for (int j = 0; j < 4; j++) {
            float v0, v1;
            unpack2(acc2[i][j], v0, v1);
            int nlo = nBase + (2 * j) * 8 + tx;
            int nhi = nBase + (2 * j + 1) * 8 + tx;
            if (EPI >= 1) { v0 += bias[nlo]; v1 += bias[nhi]; }
            if (EPI == 2) { v0 = fmaxf(v0, 0.f); v1 = fmaxf(v1, 0.f); }
            C[(size_t)m * N + nlo] = v0;
            C[(size_t)m * N + nhi] = v1;
        }
    }
}

// ------------------------- init: mask=1, key=0 ------------------------------
__global__ void init_kernel() {
    int i = blockIdx.x * blockDim.x + threadIdx.x;
    if (i < NN) g_mask[i] = 1;
    if (i == 0) g_key = 0ull;
}

// ------------------------- step-0 GEMV + argmax (verbatim R1) ---------------
__global__ void __launch_bounds__(256)
gemv_argmax_kernel(const float* __restrict__ w, const float* __restrict__ b) {
    __shared__ float sw[HH];
    __shared__ unsigned long long skey[8];
    int t = threadIdx.x;
    for (int j = t; j < HH; j += 256) sw[j] = w[j];
    __syncthreads();

    int wid = t >> 5, lane = t & 31;
    int i = blockIdx.x * 8 + wid;
    const float* row = g_gcn + (size_t)i * HH;
    float acc = 0.f;
#pragma unroll 4
    for (int jj = 0; jj < 16; jj++) {
        int j = lane + jj * 32;
        acc += row[j] * sw[j];
    }
#pragma unroll
    for (int o = 16; o; o >>= 1) acc += __shfl_down_sync(0xffffffffu, acc, o);
    if (lane == 0) {
        float v = acc + b[0];
        skey[wid] = ((unsigned long long)ford(v) << 32) |
                    (0xFFFFFFFFu - (unsigned)i);
    }
    __syncthreads();
    if (t == 0) {
        unsigned long long best = skey[0];
#pragma unroll
        for (int w2 = 1; w2 < 8; w2++) best = best > skey[w2] ? best : skey[w2];
        atomicMax(&g_key, best);
    }
}

// ------------------------- gh = h @ W_hh^T + b_hh (verbatim R1) -------------
__global__ void __launch_bounds__(256)
gh_kernel(const float* __restrict__ Whh, const float* __restrict__ bhh) {
    __shared__ float sh[HH];
    int t = threadIdx.x;
    for (int j = t; j < HH; j += 256) sh[j] = g_h[j];
    __syncthreads();
    int wid = t >> 5, lane = t & 31;
    int o = blockIdx.x * 8 + wid;
    const float* wr = Whh + (size_t)o * HH;
    float acc = 0.f;
#pragma unroll 4
    for (int jj = 0; jj < 16; jj++) {
        int j = lane + jj * 32;
        acc += wr[j] * sh[j];
    }
#pragma unroll
    for (int off = 16; off; off >>= 1)
        acc += __shfl_down_sync(0xffffffffu, acc, off);
    if (lane == 0) g_gh[o] = acc + bhh[o];
}

// ------------------------- GRU elementwise + vals + argmax (verbatim R1) ----
__global__ void __launch_bounds__(256)
gru_vals_kernel(const float* __restrict__ w2, const float* __restrict__ b2) {
    __shared__ float sgh[H3];
    __shared__ float sh[HH];
    __shared__ float sw[HH];
    __shared__ unsigned long long skey[8];
    int t = threadIdx.x;
    for (int j = t; j < H3; j += 256) sgh[j] = g_gh[j];
    for (int j = t; j < HH; j += 256) {
        sh[j] = g_h[j];
        sw[j] = w2[j];
    }
    __syncthreads();

    int wid = t >> 5, lane = t & 31;
    int i = blockIdx.x * 8 + wid;
    unsigned long long key = 0ull;
    if (g_mask[i]) {
        const float* gi = g_gi + (size_t)i * H3;
        float acc = 0.f;
#pragma unroll 4
        for (int jj = 0; jj < 16; jj++) {
            int j = lane + jj * 32;
            float r = sigf(gi[j] + sgh[j]);
            float z = sigf(gi[j + 512] + sgh[j + 512]);
            float ng = tanh_f(gi[j + 1024] + r * sgh[j + 1024]);
            float rnn = (1.f - z) * ng + z * sh[j];
            acc += sw[j] * rnn;
        }
#pragma unroll
        for (int o = 16; o; o >>= 1) acc += __shfl_down_sync(0xffffffffu, acc, o);
        if (lane == 0) {
            float v = acc + b2[0];
            key = ((unsigned long long)ford(v) << 32) |
                  (0xFFFFFFFFu - (unsigned)i);
        }
    }
    if (lane == 0) skey[wid] = key;
    __syncthreads();
    if (t == 0) {
        unsigned long long best = skey[0];
#pragma unroll
        for (int w = 1; w < 8; w++) best = best > skey[w] ? best : skey[w];
        atomicMax(&g_key, best);
    }
}

// ------------------------- select (verbatim R1) -----------------------------
__global__ void __launch_bounds__(512)
select_kernel(float* __restrict__ out, int step, int first) {
    __shared__ int sidx;
    int t = threadIdx.x;
    if (t == 0) {
        unsigned long long key = g_key;
        int idx = (int)(0xFFFFFFFFu - (unsigned)(key & 0xFFFFFFFFull));
        float v = forddec((unsigned)(key >> 32));
        out[step] = (float)idx;
        out[BS + step] = v;
        g_mask[idx] = 0;
        g_key = 0ull;
        sidx = idx;
    }
    __syncthreads();
    int idx = sidx;
    int j = t;
    if (first) {
        g_h[j] = g_gcn[(size_t)idx * HH + j];
    } else {
        const float* gi = g_gi + (size_t)idx * H3;
        float r = sigf(gi[j] + g_gh[j]);
        float z = sigf(gi[j + 512] + g_gh[j + 512]);
        float ng = tanh_f(gi[j + 1024] + r * g_gh[j + 1024]);
        g_h[j] = (1.f - z) * ng + z * g_h[j];
    }
}

// ------------------------- launch ------------------------------------------
extern "C" void kernel_launch(void* const* d_in, const int* in_sizes, int n_in,
                              void* d_out, int out_size) {
    (void)in_sizes; (void)n_in; (void)out_size;
    const float* state  = (const float*)d_in[0];
    const float* adj    = (const float*)d_in[1];
    const float* W1     = (const float*)d_in[3];
    const float* b1     = (const float*)d_in[4];
    const float* W2     = (const float*)d_in[5];
    const float* b2     = (const float*)d_in[6];
    const float* w_out1 = (const float*)d_in[7];
    const float* b_out1 = (const float*)d_in[8];
    const float* w_out2 = (const float*)d_in[9];
    const float* b_out2 = (const float*)d_in[10];
    const float* W_ih   = (const float*)d_in[11];
    const float* W_hh   = (const float*)d_in[12];
    const float* b_ih   = (const float*)d_in[13];
    const float* b_hh   = (const float*)d_in[14];
    float* out = (float*)d_out;

    float *xw, *feats, *gcn, *gi;
    cudaGetSymbolAddress((void**)&xw, g_xw);
    cudaGetSymbolAddress((void**)&feats, g_feats);
    cudaGetSymbolAddress((void**)&gcn, g_gcn);
    cudaGetSymbolAddress((void**)&gi, g_gi);

    dim3 blk(128);

    init_kernel<<<(NN + 255) / 256, 256>>>();

    // grid: x = n tiles (fast, shares A row-block in L2), y = m tiles
    // G1: XW = state @ W1
    sgemm_v5<false, 0><<<dim3(HH / TN, NN / TM), blk>>>(
        state, W1, nullptr, xw, NN, HH, HH);
    // G2: feats = relu(adj @ XW + b1)
    sgemm_v5<false, 2><<<dim3(HH / TN, NN / TM), blk>>>(
        adj, xw, b1, feats, NN, HH, NN);
    // G3: XW = feats @ W2
    sgemm_v5<false, 0><<<dim3(HH / TN, NN / TM), blk>>>(
        feats, W2, nullptr, xw, NN, HH, HH);
    // G4: gcn = relu(adj @ XW + b2)
    sgemm_v5<false, 2><<<dim3(HH / TN, NN / TM), blk>>>(
        adj, xw, b2, gcn, NN, HH, NN);
    // G5: gi = gcn @ W_ih^T + b_ih
    sgemm_v5<true, 1><<<dim3(H3 / TN, NN / TM), blk>>>(
        gcn, W_ih, b_ih, gi, NN, H3, HH);

    // step 0
    gemv_argmax_kernel<<<NN / 8, 256>>>(w_out1, b_out1);
    select_kernel<<<1, 512>>>(out, 0, 1);

    // steps 1..19
    for (int t = 1; t < BS; t++) {
        gh_kernel<<<H3 / 8, 256>>>(W_hh, b_hh);
        gru_vals_kernel<<<NN / 8, 256>>>(w_out2, b_out2);
        select_kernel<<<1, 512>>>(out, t, 0);
    }
}